// round 17
// baseline (speedup 1.0000x reference)
#include <cuda_runtime.h>
#include <cstdint>
#include <cstddef>

// Repara_PhC via sparsity (R16): persistent blocks + smem hole table + bitmask lists.
// 740 resident blocks grid-stride over 3969 64x64-px tiles. The 192-hole table
// (x, y, cutoff r^2, ex2 coeff) is loaded to smem ONCE per block. Per tile:
// warps 0-5 ballot the cutoff test (parallel, LDS-only), lane0 writes 6 mask
// words (double-buffered) -> one barrier -> all threads walk set bits in
// ascending hole order (same order as the old compacted list -> bitwise-
// identical sums). Empty tiles (mask==0) write the block-constant sigmoid via
// the same op sequence. Dense path: separable ex2 outer product, 4x4 stride-16
// microtile, dense STG runs.

#define GN     4001
#define NT     63          // 63 x 63 tiles of 64 px
#define NTILES (NT * NT)
#define TPX    64
#define NHOLES 192
#define NBLK   740         // ~5 CTAs/SM x 148 SMs, all resident
#define LOG2E  1.442695041f

__device__ __forceinline__ float ex2f(float x) {
    float r; asm("ex2.approx.ftz.f32 %0, %1;" : "=f"(r) : "f"(x)); return r;
}
__device__ __forceinline__ float rcpf(float x) {
    float r; asm("rcp.approx.ftz.f32 %0, %1;" : "=f"(r) : "f"(x)); return r;
}

__global__ __launch_bounds__(256) void eval_tiles(const float* __restrict__ holes,
                                                  const float* __restrict__ Tptr,
                                                  float* __restrict__ out) {
    __shared__ float shx[NHOLES], shy[NHOLES], shr2[NHOLES], shc[NHOLES];
    __shared__ unsigned smask[2][8];

    const int tid = threadIdx.x;
    const int tx = tid & 15;
    const int ty = tid >> 4;

    // ---- one-time: hole table -> smem ----
    if (tid < NHOLES) {
        const float cx = holes[3 * tid];
        const float cy = holes[3 * tid + 1];
        const float cs = holes[3 * tid + 2];
        shx[tid] = cx;
        shy[tid] = cy;
        shr2[tid] = 2.f * cs * cs * 16.2f;           // keep if d^2 <= r2 (exp >= ~1e-7)
        shc[tid] = -LOG2E / (2.f * cs * cs);
    }
    const float k = LOG2E * rcpf(*Tptr);
    const float vempty = rcpf(1.f + ex2f(0.5f * k)); // Z=0 path, same op sequence
    __syncthreads();

    int buf = 0;
    for (int t = blockIdx.x; t < NTILES; t += NBLK, buf ^= 1) {
        const int ti = t / NT, tj = t - ti * NT;
        const int i0 = ti * TPX, j0 = tj * TPX;

        // ---- per-tile masks: warps 0-5, parallel, LDS-only ----
        if (tid < NHOLES) {
            const float xlo = -10.f + 0.005f * (float)i0;
            const float xhi = xlo + 0.005f * (float)(TPX - 1);
            const float ylo = -10.f + 0.005f * (float)j0;
            const float yhi = ylo + 0.005f * (float)(TPX - 1);
            const float cx = shx[tid], cy = shy[tid];
            const float dx = fmaxf(fmaxf(xlo - cx, cx - xhi), 0.f);
            const float dy = fmaxf(fmaxf(ylo - cy, cy - yhi), 0.f);
            const bool in = (dx * dx + dy * dy) <= shr2[tid];
            const unsigned m = __ballot_sync(0xffffffffu, in);
            if ((tid & 31) == 0) smask[buf][tid >> 5] = m;
        }
        __syncthreads();

        unsigned mk[6];
        unsigned any = 0;
        #pragma unroll
        for (int w = 0; w < 6; ++w) { mk[w] = smask[buf][w]; any |= mk[w]; }

        if (any == 0) {
            #pragma unroll
            for (int ii = 0; ii < 4; ++ii) {
                const int i = i0 + ty + 16 * ii;
                if (i >= GN) continue;
                const uint32_t rb = (uint32_t)i * GN;
                #pragma unroll
                for (int jj = 0; jj < 4; ++jj) {
                    const int j = j0 + tx + 16 * jj;
                    if (j < GN) out[rb + j] = vempty;
                }
            }
            continue;
        }

        float xv[4], yv[4];
        #pragma unroll
        for (int ii = 0; ii < 4; ++ii) xv[ii] = -10.f + 0.005f * (float)(i0 + ty + 16 * ii);
        #pragma unroll
        for (int jj = 0; jj < 4; ++jj) yv[jj] = -10.f + 0.005f * (float)(j0 + tx + 16 * jj);

        float acc[4][4];
        #pragma unroll
        for (int ii = 0; ii < 4; ++ii)
            #pragma unroll
            for (int jj = 0; jj < 4; ++jj) acc[ii][jj] = 0.f;

        // ascending hole order == old compacted-list order -> identical sums
        #pragma unroll
        for (int w = 0; w < 6; ++w) {
            unsigned m = mk[w];
            while (m) {
                const int b = __ffs(m) - 1;
                m &= m - 1;
                const int h = w * 32 + b;
                const float hcx = shx[h], hcy = shy[h], c = shc[h];
                float ex[4], ey[4];
                #pragma unroll
                for (int ii = 0; ii < 4; ++ii) { float d = xv[ii] - hcx; ex[ii] = ex2f(d * d * c); }
                #pragma unroll
                for (int jj = 0; jj < 4; ++jj) { float d = yv[jj] - hcy; ey[jj] = ex2f(d * d * c); }
                #pragma unroll
                for (int ii = 0; ii < 4; ++ii)
                    #pragma unroll
                    for (int jj = 0; jj < 4; ++jj)
                        acc[ii][jj] = fmaf(ex[ii], ey[jj], acc[ii][jj]);
            }
        }

        // sigmoid((Z-0.5)/T) = 1/(1 + 2^((0.5-Z)*k))
        #pragma unroll
        for (int ii = 0; ii < 4; ++ii) {
            const int i = i0 + ty + 16 * ii;
            if (i >= GN) continue;
            const uint32_t rb = (uint32_t)i * GN;
            #pragma unroll
            for (int jj = 0; jj < 4; ++jj) {
                const int j = j0 + tx + 16 * jj;
                if (j < GN) {
                    float e = ex2f((0.5f - acc[ii][jj]) * k);
                    out[rb + j] = rcpf(1.f + e);
                }
            }
        }
    }
}

extern "C" void kernel_launch(void* const* d_in, const int* in_sizes, int n_in,
                              void* d_out, int out_size) {
    const float* holes = (const float*)d_in[0];   // 192 x (x0, y0, sigma)
    const float* Tptr  = (const float*)d_in[1];
    float* out = (float*)d_out;                   // 4001 x 4001 fp32

    eval_tiles<<<NBLK, 256>>>(holes, Tptr, out);
}